// round 13
// baseline (speedup 1.0000x reference)
#include <cuda_runtime.h>
#include <cuda_fp16.h>

#define HID  256
#define NG   512
#define MAXN 100000
#define MAXE 500000
#define PADK 40            // B smem row stride (fp16): 32 data + 8 pad
#define PADA 264           // A smem row stride (fp16): 256 data + 8 pad

// Scratch (device globals)
__device__ __half g_W1h[512 * 256];            // W1 transposed: [(h*256+n)][k]
__device__ __half g_W2h[256];                  // W2 in fp16
__device__ __half g_Ph[(size_t)MAXN * 512];    // P: cols 0..255 = P1+b1, 256..511 = P2
__device__ float  g_e[MAXE];                   // exp(logit)
__device__ int    g_mb[MAXE];
__device__ float  g_segsum[NG];
__device__ int    g_is64;

// ---------------------------------------------------------------------------
// init: zero segsum; thread 0 also detects index dtype
// ---------------------------------------------------------------------------
__global__ void init_kernel(const int* __restrict__ moves_i32) {
    int i = threadIdx.x;
    if (i < NG) g_segsum[i] = 0.0f;
    if (i == 0) {
        int acc = 0;
#pragma unroll 8
        for (int k = 1; k < 2048; k += 2) acc |= moves_i32[k];
        g_is64 = (acc == 0) ? 1 : 0;
    }
}

__device__ __forceinline__ long long load_idx(const void* p, size_t i, int is64) {
    if (is64) return ((const long long*)p)[i];
    return (long long)((const int*)p)[i];
}

// ---------------------------------------------------------------------------
__global__ void convert_W1_kernel(const float* __restrict__ W1,
                                  const float* __restrict__ W2) {
    int e = blockIdx.x * blockDim.x + threadIdx.x;   // 0 .. 512*256-1
    if (e < 512 * 256) {
        int r = e >> 8;          // W1 row (feature index) 0..511
        int n = e & 255;         // W1 col (output j)
        int h = r >> 8;          // half 0/1
        int k = r & 255;         // k within half
        g_W1h[(h * 256 + n) * 256 + k] = __float2half(W1[e]);
    }
    if (e < 256) g_W2h[e] = __float2half(W2[e]);
}

// ---------------------------------------------------------------------------
// fp16 GEMM, A-stripe resident + fused fp32->fp16 A conversion (unchanged R12)
// ---------------------------------------------------------------------------
__device__ __forceinline__ unsigned smem_u32(const void* p) {
    return (unsigned)__cvta_generic_to_shared(p);
}

__global__ __launch_bounds__(256) void hgemm_kernel(
    const float* __restrict__ emb, const float* __restrict__ b1, int M)
{
    extern __shared__ __half sm[];
    __half* As = sm;                        // 128 x PADA
    __half* Bs = sm + 128 * PADA;           // 4 x 128 x PADK

    int row0 = blockIdx.x * 128;
    int tid  = threadIdx.x;
    int lane = tid & 31;
    int wid  = tid >> 5;
    int wm   = wid & 1;
    int wn   = wid >> 1;

    auto issue_B = [&](int t) {
        int s  = t & 3;
        int nb = t >> 3;
        int kt = t & 7;
#pragma unroll
        for (int i = 0; i < 2; i++) {
            int c = i * 256 + tid;
            int r = c >> 2;
            int col = (c & 3) * 8;
            unsigned dst = smem_u32(Bs + s * 128 * PADK + r * PADK + col);
            const __half* src = g_W1h + (size_t)(nb * 128 + r) * 256 + kt * 32 + col;
            asm volatile("cp.async.cg.shared.global [%0], [%1], 16;\n"
                         :: "r"(dst), "l"(src));
        }
        asm volatile("cp.async.commit_group;\n");
    };

    issue_B(0);
    issue_B(1);
    issue_B(2);

    {
#pragma unroll 4
        for (int i = 0; i < 16; i++) {
            int c = i * 256 + tid;
            int r = c >> 5;
            int col = (c & 31) * 8;
            float4 v0 = make_float4(0.f, 0.f, 0.f, 0.f), v1 = v0;
            if (row0 + r < M) {
                const float4* src = (const float4*)(emb + (size_t)(row0 + r) * HID + col);
                v0 = src[0];
                v1 = src[1];
            }
            __half2 h[4];
            h[0] = __floats2half2_rn(v0.x, v0.y);
            h[1] = __floats2half2_rn(v0.z, v0.w);
            h[2] = __floats2half2_rn(v1.x, v1.y);
            h[3] = __floats2half2_rn(v1.z, v1.w);
            *(uint4*)(As + r * PADA + col) = *(const uint4*)h;
        }
    }

    float acc[4][4][4];
#pragma unroll
    for (int i = 0; i < 4; i++)
#pragma unroll
        for (int j = 0; j < 4; j++)
#pragma unroll
            for (int r = 0; r < 4; r++) acc[i][j][r] = 0.0f;

    for (int t = 0; t < 32; t++) {
        if (t < 30)       asm volatile("cp.async.wait_group 2;\n");
        else if (t == 30) asm volatile("cp.async.wait_group 1;\n");
        else              asm volatile("cp.async.wait_group 0;\n");
        __syncthreads();

        if (t + 3 < 32) issue_B(t + 3);

        const __half* Asb = As + wm * 64 * PADA;
        const __half* Bsb = Bs + (t & 3) * 128 * PADK + wn * 32 * PADK;
        int kt = t & 7;

#pragma unroll
        for (int ks = 0; ks < 2; ks++) {
            int ka = kt * 32 + ks * 16;
            int kb = ks * 16;
            unsigned af[4][4];
            unsigned bf[4][2];
#pragma unroll
            for (int mt = 0; mt < 4; mt++) {
                unsigned addr = smem_u32(Asb + (mt * 16 + (lane & 15)) * PADA + ka + (lane >> 4) * 8);
                asm volatile("ldmatrix.sync.aligned.m8n8.x4.shared.b16 {%0,%1,%2,%3}, [%4];\n"
                             : "=r"(af[mt][0]), "=r"(af[mt][1]), "=r"(af[mt][2]), "=r"(af[mt][3])
                             : "r"(addr));
            }
#pragma unroll
            for (int nt = 0; nt < 4; nt++) {
                unsigned addr = smem_u32(Bsb + (nt * 8 + (lane & 7)) * PADK + kb + ((lane >> 3) & 1) * 8);
                asm volatile("ldmatrix.sync.aligned.m8n8.x2.shared.b16 {%0,%1}, [%2];\n"
                             : "=r"(bf[nt][0]), "=r"(bf[nt][1])
                             : "r"(addr));
            }
#pragma unroll
            for (int mt = 0; mt < 4; mt++)
#pragma unroll
                for (int nt = 0; nt < 4; nt++) {
                    asm volatile(
                        "mma.sync.aligned.m16n8k16.row.col.f32.f16.f16.f32 "
                        "{%0,%1,%2,%3}, {%4,%5,%6,%7}, {%8,%9}, {%0,%1,%2,%3};\n"
                        : "+f"(acc[mt][nt][0]), "+f"(acc[mt][nt][1]),
                          "+f"(acc[mt][nt][2]), "+f"(acc[mt][nt][3])
                        : "r"(af[mt][0]), "r"(af[mt][1]), "r"(af[mt][2]), "r"(af[mt][3]),
                          "r"(bf[nt][0]), "r"(bf[nt][1]));
                }
        }

        if (kt == 7) {
            int nblk = t >> 3;
            int gcol_base = nblk * 128 + wn * 32 + (lane & 3) * 2;
            int grow_base = row0 + wm * 64 + (lane >> 2);
#pragma unroll
            for (int mt = 0; mt < 4; mt++) {
#pragma unroll
                for (int nt = 0; nt < 4; nt++) {
                    int gc = gcol_base + nt * 8;
                    float add0 = 0.0f, add1 = 0.0f;
                    if (nblk < 2) { add0 = b1[gc]; add1 = b1[gc + 1]; }
                    int r0 = grow_base + mt * 16;
                    if (r0 < M)
                        *(__half2*)(g_Ph + (size_t)r0 * 512 + gc) =
                            __floats2half2_rn(acc[mt][nt][0] + add0, acc[mt][nt][1] + add1);
                    if (r0 + 8 < M)
                        *(__half2*)(g_Ph + (size_t)(r0 + 8) * 512 + gc) =
                            __floats2half2_rn(acc[mt][nt][2] + add0, acc[mt][nt][3] + add1);
#pragma unroll
                    for (int r = 0; r < 4; r++) acc[mt][nt][r] = 0.0f;
                }
            }
        }
    }
}

// ---------------------------------------------------------------------------
// gather: 8 moves per warp (2 per 8-lane group), 16 P-row loads in flight/lane.
// No max pass; e = exp(logit) accumulated into segsum.
// ---------------------------------------------------------------------------
__device__ __forceinline__ float dot8(const uint4* a, const uint4* d, const uint4* w) {
    float acc = 0.0f;
#pragma unroll
    for (int i = 0; i < 4; i++) {
        const __half2* ah = (const __half2*)&a[i];
        const __half2* dh = (const __half2*)&d[i];
        const __half2* wh = (const __half2*)&w[i];
#pragma unroll
        for (int j = 0; j < 4; j++) {
            float2 av = __half22float2(ah[j]);
            float2 dv = __half22float2(dh[j]);
            float2 wv = __half22float2(wh[j]);
            acc += fmaxf(av.x + dv.x, 0.0f) * wv.x;
            acc += fmaxf(av.y + dv.y, 0.0f) * wv.y;
        }
    }
    return acc;
}

__global__ __launch_bounds__(256) void gather_logits_kernel(
    const void* __restrict__ moves,
    const void* __restrict__ batch,
    const float* __restrict__ b2,
    int NM)
{
    int warp = (blockIdx.x * blockDim.x + threadIdx.x) >> 5;
    int lane = threadIdx.x & 31;
    int grp  = lane >> 3;                   // 0..3
    int q    = lane & 7;                    // 0..7
    int m0   = warp * 8 + grp;
    int m1   = m0 + 4;
    bool v0 = m0 < NM, v1 = m1 < NM;
    int c0 = v0 ? m0 : 0;
    int c1 = v1 ? m1 : 0;

    int is64 = g_is64;
    long long s0 = load_idx(moves, c0, is64);
    long long t0 = load_idx(moves, (size_t)NM + c0, is64);
    long long s1 = load_idx(moves, c1, is64);
    long long t1 = load_idx(moves, (size_t)NM + c1, is64);

    const uint4* p1a = (const uint4*)(g_Ph + (size_t)s0 * 512);
    const uint4* p2a = (const uint4*)(g_Ph + (size_t)t0 * 512 + 256);
    const uint4* p1b = (const uint4*)(g_Ph + (size_t)s1 * 512);
    const uint4* p2b = (const uint4*)(g_Ph + (size_t)t1 * 512 + 256);
    const uint4* pw  = (const uint4*)g_W2h;

    uint4 a0[4], d0[4], a1[4], d1[4], uw[4];
#pragma unroll
    for (int i = 0; i < 4; i++) { a0[i] = p1a[q + 8 * i]; d0[i] = p2a[q + 8 * i]; }
#pragma unroll
    for (int i = 0; i < 4; i++) { a1[i] = p1b[q + 8 * i]; d1[i] = p2b[q + 8 * i]; }
#pragma unroll
    for (int i = 0; i < 4; i++) uw[i] = pw[q + 8 * i];

    float acc0 = dot8(a0, d0, uw);
    float acc1 = dot8(a1, d1, uw);

    acc0 += __shfl_xor_sync(0xffffffffu, acc0, 4);
    acc1 += __shfl_xor_sync(0xffffffffu, acc1, 4);
    acc0 += __shfl_xor_sync(0xffffffffu, acc0, 2);
    acc1 += __shfl_xor_sync(0xffffffffu, acc1, 2);
    acc0 += __shfl_xor_sync(0xffffffffu, acc0, 1);
    acc1 += __shfl_xor_sync(0xffffffffu, acc1, 1);

    if (q == 0) {
        float bias = b2[0];
        if (v0) {
            float e = expf(acc0 + bias);
            int g = (int)load_idx(batch, (size_t)s0, is64);
            g_e[m0] = e;
            g_mb[m0] = g;
            atomicAdd(&g_segsum[g], e);
        }
        if (v1) {
            float e = expf(acc1 + bias);
            int g = (int)load_idx(batch, (size_t)s1, is64);
            g_e[m1] = e;
            g_mb[m1] = g;
            atomicAdd(&g_segsum[g], e);
        }
    }
}

// ---------------------------------------------------------------------------
// recip: segsum -> 1/(segsum+eps); div becomes a multiply
// ---------------------------------------------------------------------------
__global__ void recip_kernel() {
    int i = threadIdx.x;
    if (i < NG) g_segsum[i] = 1.0f / (g_segsum[i] + 1e-16f);
}

__global__ void div_kernel(float* __restrict__ out, int NM) {
    int i = blockIdx.x * blockDim.x + threadIdx.x;
    int base = i * 4;
    if (base + 3 < NM) {
        float4 e = *(const float4*)(g_e + base);
        int4   g = *(const int4*)(g_mb + base);
        float4 r;
        r.x = e.x * g_segsum[g.x];
        r.y = e.y * g_segsum[g.y];
        r.z = e.z * g_segsum[g.z];
        r.w = e.w * g_segsum[g.w];
        *(float4*)(out + base) = r;
    } else {
        for (int k = base; k < NM; k++)
            out[k] = g_e[k] * g_segsum[g_mb[k]];
    }
}

// ---------------------------------------------------------------------------
extern "C" void kernel_launch(void* const* d_in, const int* in_sizes, int n_in,
                              void* d_out, int out_size)
{
    const float* emb   = (const float*)d_in[0];
    const void*  moves = d_in[1];
    const void*  batch = d_in[2];
    const float* W1    = (const float*)d_in[3];
    const float* b1    = (const float*)d_in[4];
    const float* W2    = (const float*)d_in[5];
    const float* b2    = (const float*)d_in[6];

    int M  = in_sizes[0] / HID;   // 100000
    int NM = in_sizes[1] / 2;     // 500000

    init_kernel<<<1, NG>>>((const int*)moves);
    convert_W1_kernel<<<(512 * 256 + 255) / 256, 256>>>(W1, W2);

    const int smem_bytes = (128 * PADA + 4 * 128 * PADK) * 2;   // 108544 B
    cudaFuncSetAttribute(hgemm_kernel, cudaFuncAttributeMaxDynamicSharedMemorySize, smem_bytes);
    hgemm_kernel<<<(M + 127) / 128, 256, smem_bytes>>>(emb, b1, M);

    // 8 moves per warp, 8 warps per block -> 64 moves per block
    int gblocks = (NM + 63) / 64;
    gather_logits_kernel<<<gblocks, 256>>>(moves, batch, b2, NM);

    recip_kernel<<<1, NG>>>();
    int q = (NM + 3) / 4;
    div_kernel<<<(q + 255) / 256, 256>>>((float*)d_out, NM);
}

// round 14
// speedup vs baseline: 1.0108x; 1.0108x over previous
#include <cuda_runtime.h>
#include <cuda_fp16.h>

#define HID  256
#define NG   512
#define MAXN 100000
#define MAXE 500000
#define PADK 40            // B smem row stride (fp16): 32 data + 8 pad
#define PADA 264           // A smem row stride (fp16): 256 data + 8 pad

// Scratch (device globals)
__device__ __half g_W1h[512 * 256];            // W1 transposed: [(h*256+n)][k]
__device__ __half g_W2h[256];                  // W2 in fp16
__device__ __half g_Ph[(size_t)MAXN * 512];    // P: cols 0..255 = P1+b1, 256..511 = P2
__device__ float  g_e[MAXE];                   // exp(logit)
__device__ int    g_mb[MAXE];
__device__ float  g_segsum[NG];
__device__ int    g_is64;

// ---------------------------------------------------------------------------
// init: zero segsum; thread 0 also detects index dtype
// ---------------------------------------------------------------------------
__global__ void init_kernel(const int* __restrict__ moves_i32) {
    int i = threadIdx.x;
    if (i < NG) g_segsum[i] = 0.0f;
    if (i == 0) {
        int acc = 0;
#pragma unroll 8
        for (int k = 1; k < 2048; k += 2) acc |= moves_i32[k];
        g_is64 = (acc == 0) ? 1 : 0;
    }
}

__device__ __forceinline__ long long load_idx(const void* p, size_t i, int is64) {
    if (is64) return ((const long long*)p)[i];
    return (long long)((const int*)p)[i];
}

// ---------------------------------------------------------------------------
__global__ void convert_W1_kernel(const float* __restrict__ W1,
                                  const float* __restrict__ W2) {
    int e = blockIdx.x * blockDim.x + threadIdx.x;   // 0 .. 512*256-1
    if (e < 512 * 256) {
        int r = e >> 8;          // W1 row (feature index) 0..511
        int n = e & 255;         // W1 col (output j)
        int h = r >> 8;          // half 0/1
        int k = r & 255;         // k within half
        g_W1h[(h * 256 + n) * 256 + k] = __float2half(W1[e]);
    }
    if (e < 256) g_W2h[e] = __float2half(W2[e]);
}

// ---------------------------------------------------------------------------
// fp16 GEMM, A-stripe resident + fused fp32->fp16 A conversion (unchanged)
// ---------------------------------------------------------------------------
__device__ __forceinline__ unsigned smem_u32(const void* p) {
    return (unsigned)__cvta_generic_to_shared(p);
}

__global__ __launch_bounds__(256) void hgemm_kernel(
    const float* __restrict__ emb, const float* __restrict__ b1, int M)
{
    extern __shared__ __half sm[];
    __half* As = sm;                        // 128 x PADA
    __half* Bs = sm + 128 * PADA;           // 4 x 128 x PADK

    int row0 = blockIdx.x * 128;
    int tid  = threadIdx.x;
    int lane = tid & 31;
    int wid  = tid >> 5;
    int wm   = wid & 1;
    int wn   = wid >> 1;

    auto issue_B = [&](int t) {
        int s  = t & 3;
        int nb = t >> 3;
        int kt = t & 7;
#pragma unroll
        for (int i = 0; i < 2; i++) {
            int c = i * 256 + tid;
            int r = c >> 2;
            int col = (c & 3) * 8;
            unsigned dst = smem_u32(Bs + s * 128 * PADK + r * PADK + col);
            const __half* src = g_W1h + (size_t)(nb * 128 + r) * 256 + kt * 32 + col;
            asm volatile("cp.async.cg.shared.global [%0], [%1], 16;\n"
                         :: "r"(dst), "l"(src));
        }
        asm volatile("cp.async.commit_group;\n");
    };

    issue_B(0);
    issue_B(1);
    issue_B(2);

    {
#pragma unroll 4
        for (int i = 0; i < 16; i++) {
            int c = i * 256 + tid;
            int r = c >> 5;
            int col = (c & 31) * 8;
            float4 v0 = make_float4(0.f, 0.f, 0.f, 0.f), v1 = v0;
            if (row0 + r < M) {
                const float4* src = (const float4*)(emb + (size_t)(row0 + r) * HID + col);
                v0 = src[0];
                v1 = src[1];
            }
            __half2 h[4];
            h[0] = __floats2half2_rn(v0.x, v0.y);
            h[1] = __floats2half2_rn(v0.z, v0.w);
            h[2] = __floats2half2_rn(v1.x, v1.y);
            h[3] = __floats2half2_rn(v1.z, v1.w);
            *(uint4*)(As + r * PADA + col) = *(const uint4*)h;
        }
    }

    float acc[4][4][4];
#pragma unroll
    for (int i = 0; i < 4; i++)
#pragma unroll
        for (int j = 0; j < 4; j++)
#pragma unroll
            for (int r = 0; r < 4; r++) acc[i][j][r] = 0.0f;

    for (int t = 0; t < 32; t++) {
        if (t < 30)       asm volatile("cp.async.wait_group 2;\n");
        else if (t == 30) asm volatile("cp.async.wait_group 1;\n");
        else              asm volatile("cp.async.wait_group 0;\n");
        __syncthreads();

        if (t + 3 < 32) issue_B(t + 3);

        const __half* Asb = As + wm * 64 * PADA;
        const __half* Bsb = Bs + (t & 3) * 128 * PADK + wn * 32 * PADK;
        int kt = t & 7;

#pragma unroll
        for (int ks = 0; ks < 2; ks++) {
            int ka = kt * 32 + ks * 16;
            int kb = ks * 16;
            unsigned af[4][4];
            unsigned bf[4][2];
#pragma unroll
            for (int mt = 0; mt < 4; mt++) {
                unsigned addr = smem_u32(Asb + (mt * 16 + (lane & 15)) * PADA + ka + (lane >> 4) * 8);
                asm volatile("ldmatrix.sync.aligned.m8n8.x4.shared.b16 {%0,%1,%2,%3}, [%4];\n"
                             : "=r"(af[mt][0]), "=r"(af[mt][1]), "=r"(af[mt][2]), "=r"(af[mt][3])
                             : "r"(addr));
            }
#pragma unroll
            for (int nt = 0; nt < 4; nt++) {
                unsigned addr = smem_u32(Bsb + (nt * 8 + (lane & 7)) * PADK + kb + ((lane >> 3) & 1) * 8);
                asm volatile("ldmatrix.sync.aligned.m8n8.x2.shared.b16 {%0,%1}, [%2];\n"
                             : "=r"(bf[nt][0]), "=r"(bf[nt][1])
                             : "r"(addr));
            }
#pragma unroll
            for (int mt = 0; mt < 4; mt++)
#pragma unroll
                for (int nt = 0; nt < 4; nt++) {
                    asm volatile(
                        "mma.sync.aligned.m16n8k16.row.col.f32.f16.f16.f32 "
                        "{%0,%1,%2,%3}, {%4,%5,%6,%7}, {%8,%9}, {%0,%1,%2,%3};\n"
                        : "+f"(acc[mt][nt][0]), "+f"(acc[mt][nt][1]),
                          "+f"(acc[mt][nt][2]), "+f"(acc[mt][nt][3])
                        : "r"(af[mt][0]), "r"(af[mt][1]), "r"(af[mt][2]), "r"(af[mt][3]),
                          "r"(bf[nt][0]), "r"(bf[nt][1]));
                }
        }

        if (kt == 7) {
            int nblk = t >> 3;
            int gcol_base = nblk * 128 + wn * 32 + (lane & 3) * 2;
            int grow_base = row0 + wm * 64 + (lane >> 2);
#pragma unroll
            for (int mt = 0; mt < 4; mt++) {
#pragma unroll
                for (int nt = 0; nt < 4; nt++) {
                    int gc = gcol_base + nt * 8;
                    float add0 = 0.0f, add1 = 0.0f;
                    if (nblk < 2) { add0 = b1[gc]; add1 = b1[gc + 1]; }
                    int r0 = grow_base + mt * 16;
                    if (r0 < M)
                        *(__half2*)(g_Ph + (size_t)r0 * 512 + gc) =
                            __floats2half2_rn(acc[mt][nt][0] + add0, acc[mt][nt][1] + add1);
                    if (r0 + 8 < M)
                        *(__half2*)(g_Ph + (size_t)(r0 + 8) * 512 + gc) =
                            __floats2half2_rn(acc[mt][nt][2] + add0, acc[mt][nt][3] + add1);
#pragma unroll
                    for (int r = 0; r < 4; r++) acc[mt][nt][r] = 0.0f;
                }
            }
        }
    }
}

// ---------------------------------------------------------------------------
// gather: 4 moves/warp, 8 lanes/move (R12 shape) + half2 add/relu math.
// ---------------------------------------------------------------------------
__global__ __launch_bounds__(256) void gather_logits_kernel(
    const void* __restrict__ moves,
    const void* __restrict__ batch,
    const float* __restrict__ b2,
    int NM)
{
    int warp = (blockIdx.x * blockDim.x + threadIdx.x) >> 5;
    int lane = threadIdx.x & 31;
    int grp  = lane >> 3;                   // 0..3
    int q    = lane & 7;                    // 0..7
    int m    = warp * 4 + grp;
    if (m >= NM) return;

    int is64 = g_is64;
    long long s = load_idx(moves, m, is64);
    long long t = load_idx(moves, (size_t)NM + m, is64);

    const uint4* p1 = (const uint4*)(g_Ph + (size_t)s * 512);
    const uint4* p2 = (const uint4*)(g_Ph + (size_t)t * 512 + 256);
    const uint4* pw = (const uint4*)g_W2h;

    uint4 u1[4], u2[4], uw[4];
#pragma unroll
    for (int i = 0; i < 4; i++) {
        u1[i] = p1[q + 8 * i];
        u2[i] = p2[q + 8 * i];
        uw[i] = pw[q + 8 * i];
    }

    const __half2 z2 = __float2half2_rn(0.0f);
    float acc0 = 0.0f, acc1 = 0.0f;
#pragma unroll
    for (int i = 0; i < 4; i++) {
        const __half2* a = (const __half2*)&u1[i];
        const __half2* d = (const __half2*)&u2[i];
        const __half2* w = (const __half2*)&uw[i];
#pragma unroll
        for (int j = 0; j < 4; j++) {
            __half2 p = __hmax2(__hadd2(a[j], d[j]), z2);   // add + ReLU, fp16x2
            float2 pf = __half22float2(p);
            float2 wf = __half22float2(w[j]);
            acc0 = fmaf(pf.x, wf.x, acc0);
            acc1 = fmaf(pf.y, wf.y, acc1);
        }
    }
    float acc = acc0 + acc1;

    acc += __shfl_xor_sync(0xffffffffu, acc, 4);
    acc += __shfl_xor_sync(0xffffffffu, acc, 2);
    acc += __shfl_xor_sync(0xffffffffu, acc, 1);

    if (q == 0) {
        float e = expf(acc + b2[0]);
        int g = (int)load_idx(batch, (size_t)s, is64);
        g_e[m] = e;
        g_mb[m] = g;
        atomicAdd(&g_segsum[g], e);
    }
}

// ---------------------------------------------------------------------------
__global__ void recip_kernel() {
    int i = threadIdx.x;
    if (i < NG) g_segsum[i] = 1.0f / (g_segsum[i] + 1e-16f);
}

__global__ void div_kernel(float* __restrict__ out, int NM) {
    int i = blockIdx.x * blockDim.x + threadIdx.x;
    int base = i * 4;
    if (base + 3 < NM) {
        float4 e = *(const float4*)(g_e + base);
        int4   g = *(const int4*)(g_mb + base);
        float4 r;
        r.x = e.x * g_segsum[g.x];
        r.y = e.y * g_segsum[g.y];
        r.z = e.z * g_segsum[g.z];
        r.w = e.w * g_segsum[g.w];
        *(float4*)(out + base) = r;
    } else {
        for (int k = base; k < NM; k++)
            out[k] = g_e[k] * g_segsum[g_mb[k]];
    }
}

// ---------------------------------------------------------------------------
extern "C" void kernel_launch(void* const* d_in, const int* in_sizes, int n_in,
                              void* d_out, int out_size)
{
    const float* emb   = (const float*)d_in[0];
    const void*  moves = d_in[1];
    const void*  batch = d_in[2];
    const float* W1    = (const float*)d_in[3];
    const float* b1    = (const float*)d_in[4];
    const float* W2    = (const float*)d_in[5];
    const float* b2    = (const float*)d_in[6];

    int M  = in_sizes[0] / HID;   // 100000
    int NM = in_sizes[1] / 2;     // 500000

    init_kernel<<<1, NG>>>((const int*)moves);
    convert_W1_kernel<<<(512 * 256 + 255) / 256, 256>>>(W1, W2);

    const int smem_bytes = (128 * PADA + 4 * 128 * PADK) * 2;   // 108544 B
    cudaFuncSetAttribute(hgemm_kernel, cudaFuncAttributeMaxDynamicSharedMemorySize, smem_bytes);
    hgemm_kernel<<<(M + 127) / 128, 256, smem_bytes>>>(emb, b1, M);

    int gblocks = (NM + 31) / 32;
    gather_logits_kernel<<<gblocks, 256>>>(moves, batch, b2, NM);

    recip_kernel<<<1, NG>>>();
    int q = (NM + 3) / 4;
    div_kernel<<<(q + 255) / 256, 256>>>((float*)d_out, NM);
}

// round 16
// speedup vs baseline: 1.0183x; 1.0074x over previous
#include <cuda_runtime.h>
#include <cuda_fp16.h>

#define HID  256
#define NG   512
#define MAXN 100000
#define MAXE 500000
#define PADK 40            // B smem row stride (fp16): 32 data + 8 pad
#define PADA 264           // A smem row stride (fp16): 256 data + 8 pad

// Scratch (device globals)
__device__ __half g_W1h[512 * 256];                       // W1 transposed: [(h*256+n)][k]
__device__ __align__(32) __half g_W2h[256];               // W2 in fp16
__device__ __align__(1024) __half g_Ph[(size_t)MAXN * 512]; // P: cols 0..255 = P1+b1, 256..511 = P2
__device__ float  g_e[MAXE];                              // exp(logit)
__device__ int    g_mb[MAXE];
__device__ float  g_segsum[NG];
__device__ int    g_is64;

// ---------------------------------------------------------------------------
// setup: convert W1/W2 to fp16; block 1 zeroes segsum + detects index dtype
// ---------------------------------------------------------------------------
__global__ void setup_kernel(const float* __restrict__ W1,
                             const float* __restrict__ W2,
                             const int* __restrict__ moves_i32) {
    int e = blockIdx.x * blockDim.x + threadIdx.x;   // 0 .. 512*256-1
    if (e < 512 * 256) {
        int r = e >> 8;          // W1 row (feature index) 0..511
        int n = e & 255;         // W1 col (output j)
        int h = r >> 8;          // half 0/1
        int k = r & 255;         // k within half
        g_W1h[(h * 256 + n) * 256 + k] = __float2half(W1[e]);
    }
    if (e < 256) g_W2h[e] = __float2half(W2[e]);
    if (blockIdx.x == 1) {
        int i = threadIdx.x;
        if (i < NG) g_segsum[i] = 0.0f;
        if (i == 0) {
            int acc = 0;
#pragma unroll 8
            for (int k = 1; k < 2048; k += 2) acc |= moves_i32[k];
            g_is64 = (acc == 0) ? 1 : 0;
        }
    }
}

__device__ __forceinline__ long long load_idx(const void* p, size_t i, int is64) {
    if (is64) return ((const long long*)p)[i];
    return (long long)((const int*)p)[i];
}

// ---------------------------------------------------------------------------
// fp16 GEMM, A-stripe resident + fused fp32->fp16 A conversion (R14 shape)
// ---------------------------------------------------------------------------
__device__ __forceinline__ unsigned smem_u32(const void* p) {
    return (unsigned)__cvta_generic_to_shared(p);
}

__global__ __launch_bounds__(256) void hgemm_kernel(
    const float* __restrict__ emb, const float* __restrict__ b1, int M)
{
    extern __shared__ __half sm[];
    __half* As = sm;                        // 128 x PADA
    __half* Bs = sm + 128 * PADA;           // 4 x 128 x PADK

    int row0 = blockIdx.x * 128;
    int tid  = threadIdx.x;
    int lane = tid & 31;
    int wid  = tid >> 5;
    int wm   = wid & 1;
    int wn   = wid >> 1;

    auto issue_B = [&](int t) {
        int s  = t & 3;
        int nb = t >> 3;
        int kt = t & 7;
#pragma unroll
        for (int i = 0; i < 2; i++) {
            int c = i * 256 + tid;
            int r = c >> 2;
            int col = (c & 3) * 8;
            unsigned dst = smem_u32(Bs + s * 128 * PADK + r * PADK + col);
            const __half* src = g_W1h + (size_t)(nb * 128 + r) * 256 + kt * 32 + col;
            asm volatile("cp.async.cg.shared.global [%0], [%1], 16;\n"
                         :: "r"(dst), "l"(src));
        }
        asm volatile("cp.async.commit_group;\n");
    };

    issue_B(0);
    issue_B(1);
    issue_B(2);

    {
#pragma unroll 4
        for (int i = 0; i < 16; i++) {
            int c = i * 256 + tid;
            int r = c >> 5;
            int col = (c & 31) * 8;
            float4 v0 = make_float4(0.f, 0.f, 0.f, 0.f), v1 = v0;
            if (row0 + r < M) {
                const float4* src = (const float4*)(emb + (size_t)(row0 + r) * HID + col);
                v0 = src[0];
                v1 = src[1];
            }
            __half2 h[4];
            h[0] = __floats2half2_rn(v0.x, v0.y);
            h[1] = __floats2half2_rn(v0.z, v0.w);
            h[2] = __floats2half2_rn(v1.x, v1.y);
            h[3] = __floats2half2_rn(v1.z, v1.w);
            *(uint4*)(As + r * PADA + col) = *(const uint4*)h;
        }
    }

    float acc[4][4][4];
#pragma unroll
    for (int i = 0; i < 4; i++)
#pragma unroll
        for (int j = 0; j < 4; j++)
#pragma unroll
            for (int r = 0; r < 4; r++) acc[i][j][r] = 0.0f;

    for (int t = 0; t < 32; t++) {
        if (t < 30)       asm volatile("cp.async.wait_group 2;\n");
        else if (t == 30) asm volatile("cp.async.wait_group 1;\n");
        else              asm volatile("cp.async.wait_group 0;\n");
        __syncthreads();

        if (t + 3 < 32) issue_B(t + 3);

        const __half* Asb = As + wm * 64 * PADA;
        const __half* Bsb = Bs + (t & 3) * 128 * PADK + wn * 32 * PADK;
        int kt = t & 7;

#pragma unroll
        for (int ks = 0; ks < 2; ks++) {
            int ka = kt * 32 + ks * 16;
            int kb = ks * 16;
            unsigned af[4][4];
            unsigned bf[4][2];
#pragma unroll
            for (int mt = 0; mt < 4; mt++) {
                unsigned addr = smem_u32(Asb + (mt * 16 + (lane & 15)) * PADA + ka + (lane >> 4) * 8);
                asm volatile("ldmatrix.sync.aligned.m8n8.x4.shared.b16 {%0,%1,%2,%3}, [%4];\n"
                             : "=r"(af[mt][0]), "=r"(af[mt][1]), "=r"(af[mt][2]), "=r"(af[mt][3])
                             : "r"(addr));
            }
#pragma unroll
            for (int nt = 0; nt < 4; nt++) {
                unsigned addr = smem_u32(Bsb + (nt * 8 + (lane & 7)) * PADK + kb + ((lane >> 3) & 1) * 8);
                asm volatile("ldmatrix.sync.aligned.m8n8.x2.shared.b16 {%0,%1}, [%2];\n"
                             : "=r"(bf[nt][0]), "=r"(bf[nt][1])
                             : "r"(addr));
            }
#pragma unroll
            for (int mt = 0; mt < 4; mt++)
#pragma unroll
                for (int nt = 0; nt < 4; nt++) {
                    asm volatile(
                        "mma.sync.aligned.m16n8k16.row.col.f32.f16.f16.f32 "
                        "{%0,%1,%2,%3}, {%4,%5,%6,%7}, {%8,%9}, {%0,%1,%2,%3};\n"
                        : "+f"(acc[mt][nt][0]), "+f"(acc[mt][nt][1]),
                          "+f"(acc[mt][nt][2]), "+f"(acc[mt][nt][3])
                        : "r"(af[mt][0]), "r"(af[mt][1]), "r"(af[mt][2]), "r"(af[mt][3]),
                          "r"(bf[nt][0]), "r"(bf[nt][1]));
                }
        }

        if (kt == 7) {
            int nblk = t >> 3;
            int gcol_base = nblk * 128 + wn * 32 + (lane & 3) * 2;
            int grow_base = row0 + wm * 64 + (lane >> 2);
#pragma unroll
            for (int mt = 0; mt < 4; mt++) {
#pragma unroll
                for (int nt = 0; nt < 4; nt++) {
                    int gc = gcol_base + nt * 8;
                    float add0 = 0.0f, add1 = 0.0f;
                    if (nblk < 2) { add0 = b1[gc]; add1 = b1[gc + 1]; }
                    int r0 = grow_base + mt * 16;
                    if (r0 < M)
                        *(__half2*)(g_Ph + (size_t)r0 * 512 + gc) =
                            __floats2half2_rn(acc[mt][nt][0] + add0, acc[mt][nt][1] + add1);
                    if (r0 + 8 < M)
                        *(__half2*)(g_Ph + (size_t)(r0 + 8) * 512 + gc) =
                            __floats2half2_rn(acc[mt][nt][2] + add0, acc[mt][nt][3] + add1);
#pragma unroll
                    for (int r = 0; r < 4; r++) acc[mt][nt][r] = 0.0f;
                }
            }
        }
    }
}

// ---------------------------------------------------------------------------
// gather: 4 moves/warp, 8 lanes/move, half2 math, 32B evict_last P reads.
// Lane q covers halves [q*32, q*32+32) of each 256-half P slice.
// ---------------------------------------------------------------------------
__device__ __forceinline__ ulonglong4 ld_evl_u4x64(const void* p) {
    ulonglong4 u;
    asm volatile("ld.global.nc.L2::evict_last.v4.u64 {%0,%1,%2,%3}, [%4];\n"
                 : "=l"(u.x), "=l"(u.y), "=l"(u.z), "=l"(u.w) : "l"(p));
    return u;
}

__global__ __launch_bounds__(256) void gather_logits_kernel(
    const void* __restrict__ moves,
    const void* __restrict__ batch,
    const float* __restrict__ b2,
    int NM)
{
    int warp = (blockIdx.x * blockDim.x + threadIdx.x) >> 5;
    int lane = threadIdx.x & 31;
    int grp  = lane >> 3;                   // 0..3
    int q    = lane & 7;                    // 0..7
    int m    = warp * 4 + grp;
    if (m >= NM) return;

    int is64 = g_is64;
    long long s = load_idx(moves, m, is64);
    long long t = load_idx(moves, (size_t)NM + m, is64);

    const __half* p1 = g_Ph + (size_t)s * 512 + q * 32;        // 32 halves = 64B/lane
    const __half* p2 = g_Ph + (size_t)t * 512 + 256 + q * 32;
    const __half* pw = g_W2h + q * 32;

    ulonglong4 u1[2], u2[2], uw[2];
#pragma unroll
    for (int i = 0; i < 2; i++) {
        u1[i] = ld_evl_u4x64(p1 + i * 16);
        u2[i] = ld_evl_u4x64(p2 + i * 16);
        uw[i] = *(const ulonglong4*)(pw + i * 16);
    }

    const __half2 z2 = __float2half2_rn(0.0f);
    float acc0 = 0.0f, acc1 = 0.0f;
#pragma unroll
    for (int i = 0; i < 2; i++) {
        const __half2* a = (const __half2*)&u1[i];
        const __half2* d = (const __half2*)&u2[i];
        const __half2* w = (const __half2*)&uw[i];
#pragma unroll
        for (int j = 0; j < 8; j++) {
            __half2 p = __hmax2(__hadd2(a[j], d[j]), z2);   // add + ReLU, fp16x2
            float2 pf = __half22float2(p);
            float2 wf = __half22float2(w[j]);
            acc0 = fmaf(pf.x, wf.x, acc0);
            acc1 = fmaf(pf.y, wf.y, acc1);
        }
    }
    float acc = acc0 + acc1;

    acc += __shfl_xor_sync(0xffffffffu, acc, 4);
    acc += __shfl_xor_sync(0xffffffffu, acc, 2);
    acc += __shfl_xor_sync(0xffffffffu, acc, 1);

    if (q == 0) {
        float e = expf(acc + b2[0]);
        int g = (int)load_idx(batch, (size_t)s, is64);
        g_e[m] = e;
        g_mb[m] = g;
        atomicAdd(&g_segsum[g], e);
    }
}

// ---------------------------------------------------------------------------
__global__ void recip_kernel() {
    int i = threadIdx.x;
    if (i < NG) g_segsum[i] = 1.0f / (g_segsum[i] + 1e-16f);
}

__global__ void div_kernel(float* __restrict__ out, int NM) {
    int i = blockIdx.x * blockDim.x + threadIdx.x;
    int base = i * 4;
    if (base + 3 < NM) {
        float4 e = *(const float4*)(g_e + base);
        int4   g = *(const int4*)(g_mb + base);
        float4 r;
        r.x = e.x * g_segsum[g.x];
        r.y = e.y * g_segsum[g.y];
        r.z = e.z * g_segsum[g.z];
        r.w = e.w * g_segsum[g.w];
        *(float4*)(out + base) = r;
    } else {
        for (int k = base; k < NM; k++)
            out[k] = g_e[k] * g_segsum[g_mb[k]];
    }
}

// ---------------------------------------------------------------------------
extern "C" void kernel_launch(void* const* d_in, const int* in_sizes, int n_in,
                              void* d_out, int out_size)
{
    const float* emb   = (const float*)d_in[0];
    const void*  moves = d_in[1];
    const void*  batch = d_in[2];
    const float* W1    = (const float*)d_in[3];
    const float* b1    = (const float*)d_in[4];
    const float* W2    = (const float*)d_in[5];
    const float* b2    = (const float*)d_in[6];

    int M  = in_sizes[0] / HID;   // 100000
    int NM = in_sizes[1] / 2;     // 500000

    setup_kernel<<<(512 * 256 + 255) / 256, 256>>>(W1, W2, (const int*)moves);

    const int smem_bytes = (128 * PADA + 4 * 128 * PADK) * 2;   // 108544 B
    cudaFuncSetAttribute(hgemm_kernel, cudaFuncAttributeMaxDynamicSharedMemorySize, smem_bytes);
    hgemm_kernel<<<(M + 127) / 128, 256, smem_bytes>>>(emb, b1, M);

    int gblocks = (NM + 31) / 32;
    gather_logits_kernel<<<gblocks, 256>>>(moves, batch, b2, NM);

    recip_kernel<<<1, NG>>>();
    int q = (NM + 3) / 4;
    div_kernel<<<(q + 255) / 256, 256>>>((float*)d_out, NM);
}